// round 1
// baseline (speedup 1.0000x reference)
#include <cuda_runtime.h>
#include <math.h>

// Problem dims (fixed by the dataset)
#define BB 8192   // batch B
#define HH 1024   // hidden H (== A)

// Scratch: __device__ globals (no cudaMalloc allowed)
__device__ float g_P[(size_t)BB * HH];        //  32 MB : attendee @ W_score^T + b
__device__ float g_S[(size_t)BB * BB];        // 256 MB : scores^T, then attn^T in-place
__device__ float g_ctx[(size_t)BB * HH];      //  32 MB
__device__ float g_cat[(size_t)BB * 2 * HH];  //  64 MB : concat([attender, ctx])

// ---------------------------------------------------------------------------
// NT GEMM: C[m,n] = sum_k A[m,k] * B[n,k]   (both row-major, K contiguous)
// 128x128 block tile, BK=16, 256 threads, 8x8 per thread (2x2 blocks of 4x4).
// EPI: 0 = none, 1 = +bias[n], 2 = tanh(+bias[n])
// Requires M,N % 128 == 0, K % 16 == 0 (true for all our shapes).
// ---------------------------------------------------------------------------
template <int EPI>
__global__ void __launch_bounds__(256) gemm_nt(const float* __restrict__ A,
                                               const float* __restrict__ B,
                                               float* __restrict__ C,
                                               int M, int N, int K,
                                               const float* __restrict__ bias)
{
    __shared__ float As[16][132];   // pad 132: 16B-aligned rows, mild conflicts only
    __shared__ float Bs[16][132];

    const int bm  = blockIdx.y * 128;
    const int bn  = blockIdx.x * 128;
    const int tid = threadIdx.x;
    const int tx  = tid & 15;       // 16 col-threads
    const int ty  = tid >> 4;       // 16 row-threads

    float acc[2][2][4][4];
#pragma unroll
    for (int p = 0; p < 2; p++)
#pragma unroll
        for (int q = 0; q < 2; q++)
#pragma unroll
            for (int i = 0; i < 4; i++)
#pragma unroll
                for (int j = 0; j < 4; j++) acc[p][q][i][j] = 0.f;

    const int lrow = tid >> 2;      // 0..63
    const int lc4  = tid & 3;       // float4 index within BK=16

    for (int k0 = 0; k0 < K; k0 += 16) {
#pragma unroll
        for (int l = 0; l < 2; l++) {
            const int row = lrow + l * 64;
            float4 va = *(const float4*)(A + (size_t)(bm + row) * K + k0 + lc4 * 4);
            As[lc4 * 4 + 0][row] = va.x;
            As[lc4 * 4 + 1][row] = va.y;
            As[lc4 * 4 + 2][row] = va.z;
            As[lc4 * 4 + 3][row] = va.w;
            float4 vb = *(const float4*)(B + (size_t)(bn + row) * K + k0 + lc4 * 4);
            Bs[lc4 * 4 + 0][row] = vb.x;
            Bs[lc4 * 4 + 1][row] = vb.y;
            Bs[lc4 * 4 + 2][row] = vb.z;
            Bs[lc4 * 4 + 3][row] = vb.w;
        }
        __syncthreads();
#pragma unroll
        for (int kk = 0; kk < 16; kk++) {
            float4 a0 = *(const float4*)&As[kk][ty * 4];
            float4 a1 = *(const float4*)&As[kk][64 + ty * 4];
            float4 b0 = *(const float4*)&Bs[kk][tx * 4];
            float4 b1 = *(const float4*)&Bs[kk][64 + tx * 4];
            const float ar[2][4] = {{a0.x, a0.y, a0.z, a0.w}, {a1.x, a1.y, a1.z, a1.w}};
            const float br[2][4] = {{b0.x, b0.y, b0.z, b0.w}, {b1.x, b1.y, b1.z, b1.w}};
#pragma unroll
            for (int p = 0; p < 2; p++)
#pragma unroll
                for (int q = 0; q < 2; q++)
#pragma unroll
                    for (int i = 0; i < 4; i++)
#pragma unroll
                        for (int j = 0; j < 4; j++)
                            acc[p][q][i][j] += ar[p][i] * br[q][j];
        }
        __syncthreads();
    }

#pragma unroll
    for (int p = 0; p < 2; p++)
#pragma unroll
        for (int i = 0; i < 4; i++) {
            const int row = bm + p * 64 + ty * 4 + i;
#pragma unroll
            for (int q = 0; q < 2; q++) {
                const int col = bn + q * 64 + tx * 4;
                float4 v;
                float* vp = &v.x;
#pragma unroll
                for (int j = 0; j < 4; j++) {
                    float t = acc[p][q][i][j];
                    if (EPI >= 1) t += bias[col + j];
                    if (EPI == 2) t = tanhf(t);
                    vp[j] = t;
                }
                *(float4*)(C + (size_t)row * N + col) = v;
            }
        }
}

// ---------------------------------------------------------------------------
// NN GEMM: C[m,n] = sum_k A[m,k] * B[k,n]   (both row-major)
// Same tiling as gemm_nt; B tile loaded directly (coalesced).
// ---------------------------------------------------------------------------
__global__ void __launch_bounds__(256) gemm_nn(const float* __restrict__ A,
                                               const float* __restrict__ B,
                                               float* __restrict__ C,
                                               int M, int N, int K)
{
    __shared__ float As[16][132];
    __shared__ float Bs[16][132];

    const int bm  = blockIdx.y * 128;
    const int bn  = blockIdx.x * 128;
    const int tid = threadIdx.x;
    const int tx  = tid & 15;
    const int ty  = tid >> 4;

    float acc[2][2][4][4];
#pragma unroll
    for (int p = 0; p < 2; p++)
#pragma unroll
        for (int q = 0; q < 2; q++)
#pragma unroll
            for (int i = 0; i < 4; i++)
#pragma unroll
                for (int j = 0; j < 4; j++) acc[p][q][i][j] = 0.f;

    const int lrowA = tid >> 2;   // 0..63 (A: 128 rows x 4 float4)
    const int lc4A  = tid & 3;
    const int lrowB = tid >> 5;   // 0..7  (B: 16 rows x 32 float4) -> 2 iters
    const int lc4B  = tid & 31;

    for (int k0 = 0; k0 < K; k0 += 16) {
#pragma unroll
        for (int l = 0; l < 2; l++) {
            const int row = lrowA + l * 64;
            float4 va = *(const float4*)(A + (size_t)(bm + row) * K + k0 + lc4A * 4);
            As[lc4A * 4 + 0][row] = va.x;
            As[lc4A * 4 + 1][row] = va.y;
            As[lc4A * 4 + 2][row] = va.z;
            As[lc4A * 4 + 3][row] = va.w;

            const int brow = lrowB + l * 8;
            float4 vb = *(const float4*)(B + (size_t)(k0 + brow) * N + bn + lc4B * 4);
            *(float4*)&Bs[brow][lc4B * 4] = vb;
        }
        __syncthreads();
#pragma unroll
        for (int kk = 0; kk < 16; kk++) {
            float4 a0 = *(const float4*)&As[kk][ty * 4];
            float4 a1 = *(const float4*)&As[kk][64 + ty * 4];
            float4 b0 = *(const float4*)&Bs[kk][tx * 4];
            float4 b1 = *(const float4*)&Bs[kk][64 + tx * 4];
            const float ar[2][4] = {{a0.x, a0.y, a0.z, a0.w}, {a1.x, a1.y, a1.z, a1.w}};
            const float br[2][4] = {{b0.x, b0.y, b0.z, b0.w}, {b1.x, b1.y, b1.z, b1.w}};
#pragma unroll
            for (int p = 0; p < 2; p++)
#pragma unroll
                for (int q = 0; q < 2; q++)
#pragma unroll
                    for (int i = 0; i < 4; i++)
#pragma unroll
                        for (int j = 0; j < 4; j++)
                            acc[p][q][i][j] += ar[p][i] * br[q][j];
        }
        __syncthreads();
    }

#pragma unroll
    for (int p = 0; p < 2; p++)
#pragma unroll
        for (int i = 0; i < 4; i++) {
            const int row = bm + p * 64 + ty * 4 + i;
#pragma unroll
            for (int q = 0; q < 2; q++) {
                const int col = bn + q * 64 + tx * 4;
                float4 v = make_float4(acc[p][q][i][0], acc[p][q][i][1],
                                       acc[p][q][i][2], acc[p][q][i][3]);
                *(float4*)(C + (size_t)row * N + col) = v;
            }
        }
}

// ---------------------------------------------------------------------------
// Row-wise softmax over an 8192-wide row; one block per row, values held in
// registers (single global read + single global write per element).
// ---------------------------------------------------------------------------
__global__ void __launch_bounds__(256) softmax_rows(float* __restrict__ S)
{
    __shared__ float red[8];
    const int tid = threadIdx.x;
    float* p = S + (size_t)blockIdx.x * BB;

    float4 x[8];
    float m = -3.4e38f;
#pragma unroll
    for (int it = 0; it < 8; it++) {
        x[it] = *(const float4*)(p + tid * 4 + it * 1024);
        m = fmaxf(m, fmaxf(fmaxf(x[it].x, x[it].y), fmaxf(x[it].z, x[it].w)));
    }
#pragma unroll
    for (int o = 16; o; o >>= 1) m = fmaxf(m, __shfl_xor_sync(0xffffffffu, m, o));
    if ((tid & 31) == 0) red[tid >> 5] = m;
    __syncthreads();
    m = red[0];
#pragma unroll
    for (int w = 1; w < 8; w++) m = fmaxf(m, red[w]);
    __syncthreads();   // before red reuse

    float s = 0.f;
#pragma unroll
    for (int it = 0; it < 8; it++) {
        x[it].x = expf(x[it].x - m);
        x[it].y = expf(x[it].y - m);
        x[it].z = expf(x[it].z - m);
        x[it].w = expf(x[it].w - m);
        s += (x[it].x + x[it].y) + (x[it].z + x[it].w);
    }
#pragma unroll
    for (int o = 16; o; o >>= 1) s += __shfl_xor_sync(0xffffffffu, s, o);
    if ((tid & 31) == 0) red[tid >> 5] = s;
    __syncthreads();
    s = red[0];
#pragma unroll
    for (int w = 1; w < 8; w++) s += red[w];

    const float inv = 1.0f / s;
#pragma unroll
    for (int it = 0; it < 8; it++) {
        x[it].x *= inv; x[it].y *= inv; x[it].z *= inv; x[it].w *= inv;
        *(float4*)(p + tid * 4 + it * 1024) = x[it];
    }
}

// concat([attender, ctx], axis=1) -> g_cat [BB, 2H]
__global__ void __launch_bounds__(256) concat_kernel(const float* __restrict__ a,
                                                     const float* __restrict__ c,
                                                     float* __restrict__ o)
{
    const int idx = blockIdx.x * 256 + threadIdx.x;   // one float4 each
    const int row = idx >> 9;                         // / 512 float4s per row
    const int c4  = idx & 511;
    float4 v;
    if (c4 < 256)
        v = *(const float4*)(a + (size_t)row * HH + c4 * 4);
    else
        v = *(const float4*)(c + (size_t)row * HH + (c4 - 256) * 4);
    *(float4*)(o + (size_t)row * 2 * HH + c4 * 4) = v;
}

// ---------------------------------------------------------------------------
extern "C" void kernel_launch(void* const* d_in, const int* in_sizes, int n_in,
                              void* d_out, int out_size)
{
    const float* attendee = (const float*)d_in[0];   // [B, H]
    const float* attender = (const float*)d_in[1];   // [B, H]
    const float* W_score  = (const float*)d_in[2];   // [H, H]
    const float* b_score  = (const float*)d_in[3];   // [H]
    const float* W_out    = (const float*)d_in[4];   // [A, 2H]
    const float* b_out    = (const float*)d_in[5];   // [A]
    float*       out      = (float*)d_out;           // [B, A]

    float *P, *S, *ctx, *cat;
    cudaGetSymbolAddress((void**)&P,   g_P);
    cudaGetSymbolAddress((void**)&S,   g_S);
    cudaGetSymbolAddress((void**)&ctx, g_ctx);
    cudaGetSymbolAddress((void**)&cat, g_cat);

    // 1) P = attendee @ W_score^T + b_score            [8192,1024]
    gemm_nt<1><<<dim3(HH / 128, BB / 128), 256>>>(attendee, W_score, P,
                                                  BB, HH, HH, b_score);
    // 2) S^T[j,i] = attender[j] . P[i]                 [8192,8192]
    gemm_nt<0><<<dim3(BB / 128, BB / 128), 256>>>(attender, P, S,
                                                  BB, BB, HH, nullptr);
    // 3) row softmax (== softmax(scores, axis=0) transposed)
    softmax_rows<<<BB, 256>>>(S);
    // 4) ctx = attn^T @ attendee                       [8192,1024]
    gemm_nn<<<dim3(HH / 128, BB / 128), 256>>>(S, attendee, ctx, BB, HH, BB);
    // 5) cat = concat([attender, ctx], axis=1)         [8192,2048]
    concat_kernel<<<(BB * 2 * HH / 4) / 256, 256>>>(attender, ctx, cat);
    // 6) out = tanh(cat @ W_out^T + b_out)             [8192,1024]
    gemm_nt<2><<<dim3(HH / 128, BB / 128), 256>>>(cat, W_out, out,
                                                  BB, HH, 2 * HH, b_out);
}

// round 3
// speedup vs baseline: 2.3303x; 2.3303x over previous
#include <cuda_runtime.h>
#include <cuda_bf16.h>
#include <math.h>
#include <cstdint>

#define BB 8192
#define HH 1024

// ---------------- scratch (no cudaMalloc allowed) ----------------
__device__ float          g_S  [(size_t)BB * BB];     // 256MB scores^T fp32
__device__ __nv_bfloat16  g_Shi[(size_t)BB * BB];
__device__ __nv_bfloat16  g_Slo[(size_t)BB * BB];
__device__ __nv_bfloat16  g_Ph [(size_t)BB * HH], g_Pl [(size_t)BB * HH];
__device__ __nv_bfloat16  g_aeh[(size_t)BB * HH], g_ael[(size_t)BB * HH];
__device__ __nv_bfloat16  g_aTh[(size_t)HH * BB], g_aTl[(size_t)HH * BB];
__device__ __nv_bfloat16  g_cath[(size_t)BB * 2 * HH], g_catl[(size_t)BB * 2 * HH];
__device__ __nv_bfloat16  g_Wsh[(size_t)HH * HH], g_Wsl[(size_t)HH * HH];
__device__ __nv_bfloat16  g_Woh[(size_t)HH * 2 * HH], g_Wol[(size_t)HH * 2 * HH];

// ---------------- PTX helpers (all sm_100-safe: no 'a' features) ----------------
__device__ __forceinline__ uint32_t smem_u32(const void* p) {
    uint32_t a;
    asm("{ .reg .u64 t; cvta.to.shared.u64 t, %1; cvt.u32.u64 %0, t; }" : "=r"(a) : "l"(p));
    return a;
}
__device__ __forceinline__ void cp16(uint32_t dst, const void* src) {
    asm volatile("cp.async.cg.shared.global [%0], [%1], 16;" :: "r"(dst), "l"(src) : "memory");
}
__device__ __forceinline__ void cp_commit() {
    asm volatile("cp.async.commit_group;" ::: "memory");
}
template<int N> __device__ __forceinline__ void cp_wait() {
    asm volatile("cp.async.wait_group %0;" :: "n"(N) : "memory");
}
__device__ __forceinline__ void ldsm4(uint32_t* r, uint32_t a) {
    asm volatile("ldmatrix.sync.aligned.m8n8.x4.shared.b16 {%0,%1,%2,%3}, [%4];"
                 : "=r"(r[0]), "=r"(r[1]), "=r"(r[2]), "=r"(r[3]) : "r"(a));
}
__device__ __forceinline__ void mma_bf16(float* c, const uint32_t* a, uint32_t b0, uint32_t b1) {
    asm volatile("mma.sync.aligned.m16n8k16.row.col.f32.bf16.bf16.f32 "
                 "{%0,%1,%2,%3}, {%4,%5,%6,%7}, {%8,%9}, {%0,%1,%2,%3};"
                 : "+f"(c[0]), "+f"(c[1]), "+f"(c[2]), "+f"(c[3])
                 : "r"(a[0]), "r"(a[1]), "r"(a[2]), "r"(a[3]), "r"(b0), "r"(b1));
}

// ---------------- tiling ----------------
#define TM 128
#define TN 256
#define KC 64                       // k elems per chunk (128B rows, SW128)
#define TILE_A 16384                // 128 * 128B
#define TILE_B 32768                // 256 * 128B
#define STAGE_BYTES (TILE_A + TILE_B)   // 49152
#define NSTAGE 3
#define SMEM_SZ (1024 + NSTAGE * STAGE_BYTES)

__device__ __forceinline__ uint32_t swz(uint32_t off) { return off ^ ((off >> 3) & 0x70); }

// global -> smem tile loader: R rows x 64 bf16 (128B), SW128 swizzled
template<int R>
__device__ __forceinline__ void load_tile(uint32_t sbase, const __nv_bfloat16* __restrict__ g,
                                          size_t grow, int ld, int k0, int tid)
{
    const char* gp = (const char*)(g + grow * (size_t)ld + k0);
#pragma unroll
    for (int p = 0; p < R * 8 / 256; p++) {
        int idx = p * 256 + tid;
        int row = idx >> 3, seg = idx & 7;
        cp16(sbase + swz((uint32_t)(row * 128 + seg * 16)),
             gp + (size_t)row * ld * 2 + seg * 16);
    }
}

// ---------------- split-bf16 NT GEMM via mma.sync ----------------
// D[m,n] = sum_k (Ah+Al)[m,k]*(Bh+Bl)[n,k] (drop Al*Bl), fp32 accum.
// Virtual K = 3*K with per-segment operand pointers. EPI: 0 fp32, 1 split(+bias), 2 tanh(+bias).
template<int EPI>
__global__ void __launch_bounds__(256)
gemm_mma(const __nv_bfloat16* __restrict__ Ah, const __nv_bfloat16* __restrict__ Al, int lda,
         const __nv_bfloat16* __restrict__ Bh, const __nv_bfloat16* __restrict__ Bl, int ldb,
         int K, const float* __restrict__ bias,
         float* __restrict__ Cf, __nv_bfloat16* __restrict__ Chi, __nv_bfloat16* __restrict__ Clo,
         int ldc)
{
    extern __shared__ char smem[];
    const uint32_t sb = (smem_u32(smem) + 1023) & ~1023u;

    const int tid  = threadIdx.x;
    const int wid  = tid >> 5;
    const int lane = tid & 31;
    const int wm = (wid >> 2) * 64;       // warp row offset (2 warp-rows)
    const int wn = (wid & 3) * 64;        // warp col offset (4 warp-cols)

    const size_t row0 = (size_t)blockIdx.y * TM;
    const size_t col0 = (size_t)blockIdx.x * TN;

    const __nv_bfloat16* Aseg[3] = {Ah, Al, Ah};
    const __nv_bfloat16* Bseg[3] = {Bh, Bh, Bl};
    const int nk = K / KC;
    const int nvirt = 3 * nk;

    auto issue = [&](int c, int stage) {
        const int seg = c / nk;
        const int k0  = (c - seg * nk) * KC;
        const uint32_t st = sb + (uint32_t)stage * STAGE_BYTES;
        load_tile<TM>(st,          Aseg[seg], row0, lda, k0, tid);
        load_tile<TN>(st + TILE_A, Bseg[seg], col0, ldb, k0, tid);
        cp_commit();
    };

    // ldmatrix per-lane address components (tile-local byte offsets)
    uint32_t arow128[4], brow128[4];
#pragma unroll
    for (int mi = 0; mi < 4; mi++)
        arow128[mi] = (uint32_t)((wm + mi * 16 + ((lane >> 3) & 1) * 8 + (lane & 7)) * 128);
#pragma unroll
    for (int njp = 0; njp < 4; njp++)
        brow128[njp] = (uint32_t)((wn + njp * 16 + ((lane >> 4) & 1) * 8 + (lane & 7)) * 128);
    const uint32_t acol0 = ((lane >> 4) & 1) * 16;
    const uint32_t bcol0 = ((lane >> 3) & 1) * 16;

    float acc[4][8][4];
#pragma unroll
    for (int mi = 0; mi < 4; mi++)
#pragma unroll
        for (int nj = 0; nj < 8; nj++)
#pragma unroll
            for (int e = 0; e < 4; e++) acc[mi][nj][e] = 0.f;

    issue(0, 0);
    issue(1, 1);
    issue(2, 2);   // nvirt >= 48 for all our shapes

    for (int c = 0; c < nvirt; c++) {
        const int rem = nvirt - c - 1;
        if (rem >= 2) cp_wait<2>(); else if (rem == 1) cp_wait<1>(); else cp_wait<0>();
        __syncthreads();

        const uint32_t st  = sb + (uint32_t)(c % NSTAGE) * STAGE_BYTES;
        const uint32_t sBa = st + TILE_A;
#pragma unroll
        for (int ks = 0; ks < 4; ks++) {
            uint32_t af[4][4], bf[4][4];
            const uint32_t kb = (uint32_t)(ks * 32);
#pragma unroll
            for (int mi = 0; mi < 4; mi++)
                ldsm4(af[mi], st + swz(arow128[mi] + kb + acol0));
#pragma unroll
            for (int njp = 0; njp < 4; njp++)
                ldsm4(bf[njp], sBa + swz(brow128[njp] + kb + bcol0));
#pragma unroll
            for (int mi = 0; mi < 4; mi++)
#pragma unroll
                for (int nj = 0; nj < 8; nj++)
                    mma_bf16(acc[mi][nj], af[mi], bf[nj >> 1][(nj & 1) * 2], bf[nj >> 1][(nj & 1) * 2 + 1]);
        }
        __syncthreads();
        if (c + NSTAGE < nvirt) issue(c + NSTAGE, c % NSTAGE);
    }

    // -------- epilogue --------
    const int g   = lane >> 2;
    const int tig = lane & 3;
#pragma unroll
    for (int mi = 0; mi < 4; mi++) {
        const size_t r0 = row0 + wm + mi * 16 + g;
#pragma unroll
        for (int nj = 0; nj < 8; nj++) {
            const size_t cg = col0 + wn + nj * 8 + 2 * tig;
            float f0 = acc[mi][nj][0], f1 = acc[mi][nj][1];
            float f2 = acc[mi][nj][2], f3 = acc[mi][nj][3];
            if (EPI >= 1 && bias) {
                const float b0 = bias[cg], b1 = bias[cg + 1];
                f0 += b0; f1 += b1; f2 += b0; f3 += b1;
            }
            if (EPI == 0) {
                *(float2*)(Cf + r0 * (size_t)ldc + cg)       = make_float2(f0, f1);
                *(float2*)(Cf + (r0 + 8) * (size_t)ldc + cg) = make_float2(f2, f3);
            } else if (EPI == 1) {
                __nv_bfloat16 h0 = __float2bfloat16_rn(f0), h1 = __float2bfloat16_rn(f1);
                __nv_bfloat16 h2 = __float2bfloat16_rn(f2), h3 = __float2bfloat16_rn(f3);
                __nv_bfloat16 l0 = __float2bfloat16_rn(f0 - __bfloat162float(h0));
                __nv_bfloat16 l1 = __float2bfloat16_rn(f1 - __bfloat162float(h1));
                __nv_bfloat16 l2 = __float2bfloat16_rn(f2 - __bfloat162float(h2));
                __nv_bfloat16 l3 = __float2bfloat16_rn(f3 - __bfloat162float(h3));
                __nv_bfloat162 hv0 = __halves2bfloat162(h0, h1), hv1 = __halves2bfloat162(h2, h3);
                __nv_bfloat162 lv0 = __halves2bfloat162(l0, l1), lv1 = __halves2bfloat162(l2, l3);
                *(uint32_t*)(Chi + r0 * (size_t)ldc + cg)       = *(uint32_t*)&hv0;
                *(uint32_t*)(Chi + (r0 + 8) * (size_t)ldc + cg) = *(uint32_t*)&hv1;
                *(uint32_t*)(Clo + r0 * (size_t)ldc + cg)       = *(uint32_t*)&lv0;
                *(uint32_t*)(Clo + (r0 + 8) * (size_t)ldc + cg) = *(uint32_t*)&lv1;
            } else {
                *(float2*)(Cf + r0 * (size_t)ldc + cg)       = make_float2(tanhf(f0), tanhf(f1));
                *(float2*)(Cf + (r0 + 8) * (size_t)ldc + cg) = make_float2(tanhf(f2), tanhf(f3));
            }
        }
    }
}

// ---------------- split fp32 -> bf16 hi/lo (strided dst) ----------------
__global__ void __launch_bounds__(256) split_strided(const float* __restrict__ src,
                                                     __nv_bfloat16* __restrict__ hi,
                                                     __nv_bfloat16* __restrict__ lo,
                                                     int cols, int dst_ld)
{
    const size_t idx = ((size_t)blockIdx.x * 256 + threadIdx.x) * 4;
    const size_t row = idx / cols;
    const int col = (int)(idx % cols);
    float4 v = *(const float4*)(src + idx);
    const float f[4] = {v.x, v.y, v.z, v.w};
    uint32_t hp[2], lp[2];
#pragma unroll
    for (int j = 0; j < 2; j++) {
        __nv_bfloat16 h0 = __float2bfloat16_rn(f[2*j]);
        __nv_bfloat16 h1 = __float2bfloat16_rn(f[2*j+1]);
        __nv_bfloat16 l0 = __float2bfloat16_rn(f[2*j] - __bfloat162float(h0));
        __nv_bfloat16 l1 = __float2bfloat16_rn(f[2*j+1] - __bfloat162float(h1));
        __nv_bfloat162 hv = __halves2bfloat162(h0, h1);
        __nv_bfloat162 lv = __halves2bfloat162(l0, l1);
        hp[j] = *(uint32_t*)&hv; lp[j] = *(uint32_t*)&lv;
    }
    *(uint2*)(hi + row * (size_t)dst_ld + col) = make_uint2(hp[0], hp[1]);
    *(uint2*)(lo + row * (size_t)dst_ld + col) = make_uint2(lp[0], lp[1]);
}

// ---------------- transpose + split: attendee -> aT [1024,8192] ----------------
__global__ void __launch_bounds__(256) transpose_split(const float* __restrict__ src,
                                                       __nv_bfloat16* __restrict__ hi,
                                                       __nv_bfloat16* __restrict__ lo)
{
    __shared__ float t[32][33];
    const int tx = threadIdx.x, ty = threadIdx.y;
    const int c0 = blockIdx.x * 32;
    const int r0 = blockIdx.y * 32;
#pragma unroll
    for (int j = 0; j < 4; j++)
        t[ty + 8*j][tx] = src[(size_t)(r0 + ty + 8*j) * HH + c0 + tx];
    __syncthreads();
#pragma unroll
    for (int j = 0; j < 4; j++) {
        float v = t[tx][ty + 8*j];
        __nv_bfloat16 h = __float2bfloat16_rn(v);
        __nv_bfloat16 l = __float2bfloat16_rn(v - __bfloat162float(h));
        const size_t o = (size_t)(c0 + ty + 8*j) * BB + r0 + tx;
        hi[o] = h; lo[o] = l;
    }
}

// ---------------- softmax rows + split to bf16 hi/lo ----------------
__global__ void __launch_bounds__(256) softmax_split(const float* __restrict__ S,
                                                     __nv_bfloat16* __restrict__ hi,
                                                     __nv_bfloat16* __restrict__ lo)
{
    __shared__ float red[8];
    const int tid = threadIdx.x;
    const float* p = S + (size_t)blockIdx.x * BB;
    const size_t ob = (size_t)blockIdx.x * BB;

    float4 x[8];
    float m = -3.4e38f;
#pragma unroll
    for (int it = 0; it < 8; it++) {
        x[it] = *(const float4*)(p + tid * 4 + it * 1024);
        m = fmaxf(m, fmaxf(fmaxf(x[it].x, x[it].y), fmaxf(x[it].z, x[it].w)));
    }
#pragma unroll
    for (int o = 16; o; o >>= 1) m = fmaxf(m, __shfl_xor_sync(0xffffffffu, m, o));
    if ((tid & 31) == 0) red[tid >> 5] = m;
    __syncthreads();
    m = red[0];
#pragma unroll
    for (int w = 1; w < 8; w++) m = fmaxf(m, red[w]);
    __syncthreads();

    float s = 0.f;
#pragma unroll
    for (int it = 0; it < 8; it++) {
        x[it].x = expf(x[it].x - m); x[it].y = expf(x[it].y - m);
        x[it].z = expf(x[it].z - m); x[it].w = expf(x[it].w - m);
        s += (x[it].x + x[it].y) + (x[it].z + x[it].w);
    }
#pragma unroll
    for (int o = 16; o; o >>= 1) s += __shfl_xor_sync(0xffffffffu, s, o);
    if ((tid & 31) == 0) red[tid >> 5] = s;
    __syncthreads();
    s = red[0];
#pragma unroll
    for (int w = 1; w < 8; w++) s += red[w];
    const float inv = 1.0f / s;

#pragma unroll
    for (int it = 0; it < 8; it++) {
        const float f[4] = {x[it].x * inv, x[it].y * inv, x[it].z * inv, x[it].w * inv};
        uint32_t hp[2], lp[2];
#pragma unroll
        for (int j = 0; j < 2; j++) {
            __nv_bfloat16 h0 = __float2bfloat16_rn(f[2*j]);
            __nv_bfloat16 h1 = __float2bfloat16_rn(f[2*j+1]);
            __nv_bfloat16 l0 = __float2bfloat16_rn(f[2*j] - __bfloat162float(h0));
            __nv_bfloat16 l1 = __float2bfloat16_rn(f[2*j+1] - __bfloat162float(h1));
            __nv_bfloat162 hv = __halves2bfloat162(h0, h1);
            __nv_bfloat162 lv = __halves2bfloat162(l0, l1);
            hp[j] = *(uint32_t*)&hv; lp[j] = *(uint32_t*)&lv;
        }
        *(uint2*)(hi + ob + tid * 4 + it * 1024) = make_uint2(hp[0], hp[1]);
        *(uint2*)(lo + ob + tid * 4 + it * 1024) = make_uint2(lp[0], lp[1]);
    }
}

// ---------------------------------------------------------------------------
extern "C" void kernel_launch(void* const* d_in, const int* in_sizes, int n_in,
                              void* d_out, int out_size)
{
    const float* attendee = (const float*)d_in[0];
    const float* attender = (const float*)d_in[1];
    const float* W_score  = (const float*)d_in[2];
    const float* b_score  = (const float*)d_in[3];
    const float* W_out    = (const float*)d_in[4];
    const float* b_out    = (const float*)d_in[5];
    float*       out      = (float*)d_out;

    float* S;
    __nv_bfloat16 *Shi, *Slo, *Ph, *Pl, *aeh, *ael, *aTh, *aTl, *cath, *catl, *Wsh, *Wsl, *Woh, *Wol;
    cudaGetSymbolAddress((void**)&S,    g_S);
    cudaGetSymbolAddress((void**)&Shi,  g_Shi);
    cudaGetSymbolAddress((void**)&Slo,  g_Slo);
    cudaGetSymbolAddress((void**)&Ph,   g_Ph);
    cudaGetSymbolAddress((void**)&Pl,   g_Pl);
    cudaGetSymbolAddress((void**)&aeh,  g_aeh);
    cudaGetSymbolAddress((void**)&ael,  g_ael);
    cudaGetSymbolAddress((void**)&aTh,  g_aTh);
    cudaGetSymbolAddress((void**)&aTl,  g_aTl);
    cudaGetSymbolAddress((void**)&cath, g_cath);
    cudaGetSymbolAddress((void**)&catl, g_catl);
    cudaGetSymbolAddress((void**)&Wsh,  g_Wsh);
    cudaGetSymbolAddress((void**)&Wsl,  g_Wsl);
    cudaGetSymbolAddress((void**)&Woh,  g_Woh);
    cudaGetSymbolAddress((void**)&Wol,  g_Wol);

    cudaFuncSetAttribute(gemm_mma<0>, cudaFuncAttributeMaxDynamicSharedMemorySize, SMEM_SZ);
    cudaFuncSetAttribute(gemm_mma<1>, cudaFuncAttributeMaxDynamicSharedMemorySize, SMEM_SZ);
    cudaFuncSetAttribute(gemm_mma<2>, cudaFuncAttributeMaxDynamicSharedMemorySize, SMEM_SZ);

    // operand splits
    split_strided<<<(BB * HH) / 1024, 256>>>(attendee, aeh, ael, HH, HH);
    split_strided<<<(BB * HH) / 1024, 256>>>(attender, cath, catl, HH, 2 * HH);
    split_strided<<<(HH * HH) / 1024, 256>>>(W_score, Wsh, Wsl, HH, HH);
    split_strided<<<(HH * 2 * HH) / 1024, 256>>>(W_out, Woh, Wol, 2 * HH, 2 * HH);
    transpose_split<<<dim3(HH / 32, BB / 32), dim3(32, 8)>>>(attendee, aTh, aTl);

    // 1) P = attendee @ W_score^T + b_score  -> Ph/Pl              [8192,1024]
    gemm_mma<1><<<dim3(HH / TN, BB / TM), 256, SMEM_SZ>>>(
        aeh, ael, HH, Wsh, Wsl, HH, HH, b_score, nullptr, Ph, Pl, HH);
    // 2) S[j,i] = attender_j . P_i (fp32)                          [8192,8192]
    gemm_mma<0><<<dim3(BB / TN, BB / TM), 256, SMEM_SZ>>>(
        cath, catl, 2 * HH, Ph, Pl, HH, HH, nullptr, S, nullptr, nullptr, BB);
    // 3) softmax rows + split -> Shi/Slo
    softmax_split<<<BB, 256>>>(S, Shi, Slo);
    // 4) ctx = attn-rows @ attendee^T  -> cat cols [1024,2048)     [8192,1024]
    gemm_mma<1><<<dim3(HH / TN, BB / TM), 256, SMEM_SZ>>>(
        Shi, Slo, BB, aTh, aTl, BB, BB, nullptr, nullptr, cath + HH, catl + HH, 2 * HH);
    // 5) out = tanh(cat @ W_out^T + b_out)                         [8192,1024]
    gemm_mma<2><<<dim3(HH / TN, BB / TM), 256, SMEM_SZ>>>(
        cath, catl, 2 * HH, Woh, Wol, 2 * HH, 2 * HH, b_out, out, nullptr, nullptr, HH);
}

// round 4
// speedup vs baseline: 2.5839x; 1.1089x over previous
#include <cuda_runtime.h>
#include <cuda_bf16.h>
#include <math.h>
#include <cstdint>

#define BB 8192
#define HH 1024

// ---------------- scratch (no cudaMalloc allowed) ----------------
__device__ float          g_S  [(size_t)BB * BB];     // 256MB scores^T fp32
__device__ __nv_bfloat16  g_Shi[(size_t)BB * BB];
__device__ __nv_bfloat16  g_Slo[(size_t)BB * BB];
__device__ __nv_bfloat16  g_Ph [(size_t)BB * HH], g_Pl [(size_t)BB * HH];
__device__ __nv_bfloat16  g_aeh[(size_t)BB * HH], g_ael[(size_t)BB * HH];
__device__ __nv_bfloat16  g_aTh[(size_t)HH * BB], g_aTl[(size_t)HH * BB];
__device__ __nv_bfloat16  g_cath[(size_t)BB * 2 * HH], g_catl[(size_t)BB * 2 * HH];
__device__ __nv_bfloat16  g_Wsh[(size_t)HH * HH], g_Wsl[(size_t)HH * HH];
__device__ __nv_bfloat16  g_Woh[(size_t)HH * 2 * HH], g_Wol[(size_t)HH * 2 * HH];

// ---------------- PTX helpers (all sm_100-safe: no 'a' features) ----------------
__device__ __forceinline__ uint32_t smem_u32(const void* p) {
    uint32_t a;
    asm("{ .reg .u64 t; cvta.to.shared.u64 t, %1; cvt.u32.u64 %0, t; }" : "=r"(a) : "l"(p));
    return a;
}
__device__ __forceinline__ void cp16(uint32_t dst, const void* src) {
    asm volatile("cp.async.cg.shared.global [%0], [%1], 16;" :: "r"(dst), "l"(src) : "memory");
}
__device__ __forceinline__ void cp_commit() {
    asm volatile("cp.async.commit_group;" ::: "memory");
}
template<int N> __device__ __forceinline__ void cp_wait() {
    asm volatile("cp.async.wait_group %0;" :: "n"(N) : "memory");
}
__device__ __forceinline__ void ldsm4(uint32_t* r, uint32_t a) {
    asm volatile("ldmatrix.sync.aligned.m8n8.x4.shared.b16 {%0,%1,%2,%3}, [%4];"
                 : "=r"(r[0]), "=r"(r[1]), "=r"(r[2]), "=r"(r[3]) : "r"(a));
}
__device__ __forceinline__ void mma_bf16(float* c, const uint32_t* a, uint32_t b0, uint32_t b1) {
    asm volatile("mma.sync.aligned.m16n8k16.row.col.f32.bf16.bf16.f32 "
                 "{%0,%1,%2,%3}, {%4,%5,%6,%7}, {%8,%9}, {%0,%1,%2,%3};"
                 : "+f"(c[0]), "+f"(c[1]), "+f"(c[2]), "+f"(c[3])
                 : "r"(a[0]), "r"(a[1]), "r"(a[2]), "r"(a[3]), "r"(b0), "r"(b1));
}

// ---------------- tiling ----------------
#define TM 128
#define TN 256
#define KC 64                       // k elems per chunk (128B rows, SW128)
#define TILE_A 16384                // 128 * 128B
#define TILE_B 32768                // 256 * 128B
#define STAGE_BYTES (TILE_A + TILE_B)   // 49152
#define NSTAGE 4
#define SMEM_SZ (1024 + NSTAGE * STAGE_BYTES)   // 197632 <= 227KB dyn limit

__device__ __forceinline__ uint32_t swz(uint32_t off) { return off ^ ((off >> 3) & 0x70); }

// global -> smem tile loader: R rows x 64 bf16 (128B), SW128 swizzled
template<int R>
__device__ __forceinline__ void load_tile(uint32_t sbase, const __nv_bfloat16* __restrict__ g,
                                          size_t grow, int ld, int k0, int tid)
{
    const char* gp = (const char*)(g + grow * (size_t)ld + k0);
#pragma unroll
    for (int p = 0; p < R * 8 / 256; p++) {
        int idx = p * 256 + tid;
        int row = idx >> 3, seg = idx & 7;
        cp16(sbase + swz((uint32_t)(row * 128 + seg * 16)),
             gp + (size_t)row * ld * 2 + seg * 16);
    }
}

// ---------------- split-bf16 NT GEMM via mma.sync ----------------
// D[m,n] = sum_k (Ah+Al)[m,k]*(Bh+Bl)[n,k] (drop Al*Bl), fp32 accum.
// Virtual K = 3*K with per-segment operand pointers.
// 4-stage cp.async pipeline, load-issue BEFORE compute, one barrier per chunk.
// EPI: 0 fp32, 1 split(+bias), 2 tanh(+bias).
template<int EPI>
__global__ void __launch_bounds__(256, 1)
gemm_mma(const __nv_bfloat16* __restrict__ Ah, const __nv_bfloat16* __restrict__ Al, int lda,
         const __nv_bfloat16* __restrict__ Bh, const __nv_bfloat16* __restrict__ Bl, int ldb,
         int K, const float* __restrict__ bias,
         float* __restrict__ Cf, __nv_bfloat16* __restrict__ Chi, __nv_bfloat16* __restrict__ Clo,
         int ldc)
{
    extern __shared__ char smem[];
    const uint32_t sb = (smem_u32(smem) + 1023) & ~1023u;

    const int tid  = threadIdx.x;
    const int wid  = tid >> 5;
    const int lane = tid & 31;
    const int wm = (wid >> 2) * 64;       // warp row offset (2 warp-rows)
    const int wn = (wid & 3) * 64;        // warp col offset (4 warp-cols)

    const size_t row0 = (size_t)blockIdx.y * TM;
    const size_t col0 = (size_t)blockIdx.x * TN;

    const __nv_bfloat16* Aseg[3] = {Ah, Al, Ah};
    const __nv_bfloat16* Bseg[3] = {Bh, Bh, Bl};
    const int nk = K / KC;
    const int nvirt = 3 * nk;

    auto issue = [&](int c) {
        const int seg = c / nk;
        const int k0  = (c - seg * nk) * KC;
        const uint32_t st = sb + (uint32_t)(c & (NSTAGE - 1)) * STAGE_BYTES;
        load_tile<TM>(st,          Aseg[seg], row0, lda, k0, tid);
        load_tile<TN>(st + TILE_A, Bseg[seg], col0, ldb, k0, tid);
        cp_commit();
    };

    // ldmatrix per-lane address components (tile-local byte offsets)
    uint32_t arow128[4], brow128[4];
#pragma unroll
    for (int mi = 0; mi < 4; mi++)
        arow128[mi] = (uint32_t)((wm + mi * 16 + ((lane >> 3) & 1) * 8 + (lane & 7)) * 128);
#pragma unroll
    for (int njp = 0; njp < 4; njp++)
        brow128[njp] = (uint32_t)((wn + njp * 16 + ((lane >> 4) & 1) * 8 + (lane & 7)) * 128);
    const uint32_t acol0 = ((lane >> 4) & 1) * 16;
    const uint32_t bcol0 = ((lane >> 3) & 1) * 16;

    float acc[4][8][4];
#pragma unroll
    for (int mi = 0; mi < 4; mi++)
#pragma unroll
        for (int nj = 0; nj < 8; nj++)
#pragma unroll
            for (int e = 0; e < 4; e++) acc[mi][nj][e] = 0.f;

    // prologue: 3 chunks in flight (4th buffer stays free for issue-before-compute)
    issue(0);
    issue(1);
    issue(2);   // nvirt >= 48 for all our shapes

    for (int c = 0; c < nvirt; c++) {
        const int rem = nvirt - c - 1;
        if (rem >= 2) cp_wait<2>(); else if (rem == 1) cp_wait<1>(); else cp_wait<0>();
        __syncthreads();   // all warps done reading stage (c-1)%4 == (c+3)%4

        if (c + 3 < nvirt) issue(c + 3);   // DMA overlaps with this chunk's MMAs

        const uint32_t st  = sb + (uint32_t)(c & (NSTAGE - 1)) * STAGE_BYTES;
        const uint32_t sBa = st + TILE_A;
#pragma unroll
        for (int ks = 0; ks < 4; ks++) {
            uint32_t af[4][4], bf[4][4];
            const uint32_t kb = (uint32_t)(ks * 32);
#pragma unroll
            for (int mi = 0; mi < 4; mi++)
                ldsm4(af[mi], st + swz(arow128[mi] + kb + acol0));
#pragma unroll
            for (int njp = 0; njp < 4; njp++)
                ldsm4(bf[njp], sBa + swz(brow128[njp] + kb + bcol0));
#pragma unroll
            for (int mi = 0; mi < 4; mi++)
#pragma unroll
                for (int nj = 0; nj < 8; nj++)
                    mma_bf16(acc[mi][nj], af[mi], bf[nj >> 1][(nj & 1) * 2], bf[nj >> 1][(nj & 1) * 2 + 1]);
        }
    }

    // -------- epilogue --------
    const int g   = lane >> 2;
    const int tig = lane & 3;
#pragma unroll
    for (int mi = 0; mi < 4; mi++) {
        const size_t r0 = row0 + wm + mi * 16 + g;
#pragma unroll
        for (int nj = 0; nj < 8; nj++) {
            const size_t cg = col0 + wn + nj * 8 + 2 * tig;
            float f0 = acc[mi][nj][0], f1 = acc[mi][nj][1];
            float f2 = acc[mi][nj][2], f3 = acc[mi][nj][3];
            if (EPI >= 1 && bias) {
                const float b0 = bias[cg], b1 = bias[cg + 1];
                f0 += b0; f1 += b1; f2 += b0; f3 += b1;
            }
            if (EPI == 0) {
                *(float2*)(Cf + r0 * (size_t)ldc + cg)       = make_float2(f0, f1);
                *(float2*)(Cf + (r0 + 8) * (size_t)ldc + cg) = make_float2(f2, f3);
            } else if (EPI == 1) {
                __nv_bfloat16 h0 = __float2bfloat16_rn(f0), h1 = __float2bfloat16_rn(f1);
                __nv_bfloat16 h2 = __float2bfloat16_rn(f2), h3 = __float2bfloat16_rn(f3);
                __nv_bfloat16 l0 = __float2bfloat16_rn(f0 - __bfloat162float(h0));
                __nv_bfloat16 l1 = __float2bfloat16_rn(f1 - __bfloat162float(h1));
                __nv_bfloat16 l2 = __float2bfloat16_rn(f2 - __bfloat162float(h2));
                __nv_bfloat16 l3 = __float2bfloat16_rn(f3 - __bfloat162float(h3));
                __nv_bfloat162 hv0 = __halves2bfloat162(h0, h1), hv1 = __halves2bfloat162(h2, h3);
                __nv_bfloat162 lv0 = __halves2bfloat162(l0, l1), lv1 = __halves2bfloat162(l2, l3);
                *(uint32_t*)(Chi + r0 * (size_t)ldc + cg)       = *(uint32_t*)&hv0;
                *(uint32_t*)(Chi + (r0 + 8) * (size_t)ldc + cg) = *(uint32_t*)&hv1;
                *(uint32_t*)(Clo + r0 * (size_t)ldc + cg)       = *(uint32_t*)&lv0;
                *(uint32_t*)(Clo + (r0 + 8) * (size_t)ldc + cg) = *(uint32_t*)&lv1;
            } else {
                *(float2*)(Cf + r0 * (size_t)ldc + cg)       = make_float2(tanhf(f0), tanhf(f1));
                *(float2*)(Cf + (r0 + 8) * (size_t)ldc + cg) = make_float2(tanhf(f2), tanhf(f3));
            }
        }
    }
}

// ---------------- split fp32 -> bf16 hi/lo (strided dst) ----------------
__global__ void __launch_bounds__(256) split_strided(const float* __restrict__ src,
                                                     __nv_bfloat16* __restrict__ hi,
                                                     __nv_bfloat16* __restrict__ lo,
                                                     int cols, int dst_ld)
{
    const size_t idx = ((size_t)blockIdx.x * 256 + threadIdx.x) * 4;
    const size_t row = idx / cols;
    const int col = (int)(idx % cols);
    float4 v = *(const float4*)(src + idx);
    const float f[4] = {v.x, v.y, v.z, v.w};
    uint32_t hp[2], lp[2];
#pragma unroll
    for (int j = 0; j < 2; j++) {
        __nv_bfloat16 h0 = __float2bfloat16_rn(f[2*j]);
        __nv_bfloat16 h1 = __float2bfloat16_rn(f[2*j+1]);
        __nv_bfloat16 l0 = __float2bfloat16_rn(f[2*j] - __bfloat162float(h0));
        __nv_bfloat16 l1 = __float2bfloat16_rn(f[2*j+1] - __bfloat162float(h1));
        __nv_bfloat162 hv = __halves2bfloat162(h0, h1);
        __nv_bfloat162 lv = __halves2bfloat162(l0, l1);
        hp[j] = *(uint32_t*)&hv; lp[j] = *(uint32_t*)&lv;
    }
    *(uint2*)(hi + row * (size_t)dst_ld + col) = make_uint2(hp[0], hp[1]);
    *(uint2*)(lo + row * (size_t)dst_ld + col) = make_uint2(lp[0], lp[1]);
}

// ---------------- transpose + split: attendee -> aT [1024,8192] ----------------
__global__ void __launch_bounds__(256) transpose_split(const float* __restrict__ src,
                                                       __nv_bfloat16* __restrict__ hi,
                                                       __nv_bfloat16* __restrict__ lo)
{
    __shared__ float t[32][33];
    const int tx = threadIdx.x, ty = threadIdx.y;
    const int c0 = blockIdx.x * 32;
    const int r0 = blockIdx.y * 32;
#pragma unroll
    for (int j = 0; j < 4; j++)
        t[ty + 8*j][tx] = src[(size_t)(r0 + ty + 8*j) * HH + c0 + tx];
    __syncthreads();
#pragma unroll
    for (int j = 0; j < 4; j++) {
        float v = t[tx][ty + 8*j];
        __nv_bfloat16 h = __float2bfloat16_rn(v);
        __nv_bfloat16 l = __float2bfloat16_rn(v - __bfloat162float(h));
        const size_t o = (size_t)(c0 + ty + 8*j) * BB + r0 + tx;
        hi[o] = h; lo[o] = l;
    }
}

// ---------------- softmax rows + split to bf16 hi/lo ----------------
__global__ void __launch_bounds__(256) softmax_split(const float* __restrict__ S,
                                                     __nv_bfloat16* __restrict__ hi,
                                                     __nv_bfloat16* __restrict__ lo)
{
    __shared__ float red[8];
    const int tid = threadIdx.x;
    const float* p = S + (size_t)blockIdx.x * BB;
    const size_t ob = (size_t)blockIdx.x * BB;

    float4 x[8];
    float m = -3.4e38f;
#pragma unroll
    for (int it = 0; it < 8; it++) {
        x[it] = *(const float4*)(p + tid * 4 + it * 1024);
        m = fmaxf(m, fmaxf(fmaxf(x[it].x, x[it].y), fmaxf(x[it].z, x[it].w)));
    }
#pragma unroll
    for (int o = 16; o; o >>= 1) m = fmaxf(m, __shfl_xor_sync(0xffffffffu, m, o));
    if ((tid & 31) == 0) red[tid >> 5] = m;
    __syncthreads();
    m = red[0];
#pragma unroll
    for (int w = 1; w < 8; w++) m = fmaxf(m, red[w]);
    __syncthreads();

    float s = 0.f;
#pragma unroll
    for (int it = 0; it < 8; it++) {
        x[it].x = expf(x[it].x - m); x[it].y = expf(x[it].y - m);
        x[it].z = expf(x[it].z - m); x[it].w = expf(x[it].w - m);
        s += (x[it].x + x[it].y) + (x[it].z + x[it].w);
    }
#pragma unroll
    for (int o = 16; o; o >>= 1) s += __shfl_xor_sync(0xffffffffu, s, o);
    if ((tid & 31) == 0) red[tid >> 5] = s;
    __syncthreads();
    s = red[0];
#pragma unroll
    for (int w = 1; w < 8; w++) s += red[w];
    const float inv = 1.0f / s;

#pragma unroll
    for (int it = 0; it < 8; it++) {
        const float f[4] = {x[it].x * inv, x[it].y * inv, x[it].z * inv, x[it].w * inv};
        uint32_t hp[2], lp[2];
#pragma unroll
        for (int j = 0; j < 2; j++) {
            __nv_bfloat16 h0 = __float2bfloat16_rn(f[2*j]);
            __nv_bfloat16 h1 = __float2bfloat16_rn(f[2*j+1]);
            __nv_bfloat16 l0 = __float2bfloat16_rn(f[2*j] - __bfloat162float(h0));
            __nv_bfloat16 l1 = __float2bfloat16_rn(f[2*j+1] - __bfloat162float(h1));
            __nv_bfloat162 hv = __halves2bfloat162(h0, h1);
            __nv_bfloat162 lv = __halves2bfloat162(l0, l1);
            hp[j] = *(uint32_t*)&hv; lp[j] = *(uint32_t*)&lv;
        }
        *(uint2*)(hi + ob + tid * 4 + it * 1024) = make_uint2(hp[0], hp[1]);
        *(uint2*)(lo + ob + tid * 4 + it * 1024) = make_uint2(lp[0], lp[1]);
    }
}

// ---------------------------------------------------------------------------
extern "C" void kernel_launch(void* const* d_in, const int* in_sizes, int n_in,
                              void* d_out, int out_size)
{
    const float* attendee = (const float*)d_in[0];
    const float* attender = (const float*)d_in[1];
    const float* W_score  = (const float*)d_in[2];
    const float* b_score  = (const float*)d_in[3];
    const float* W_out    = (const float*)d_in[4];
    const float* b_out    = (const float*)d_in[5];
    float*       out      = (float*)d_out;

    float* S;
    __nv_bfloat16 *Shi, *Slo, *Ph, *Pl, *aeh, *ael, *aTh, *aTl, *cath, *catl, *Wsh, *Wsl, *Woh, *Wol;
    cudaGetSymbolAddress((void**)&S,    g_S);
    cudaGetSymbolAddress((void**)&Shi,  g_Shi);
    cudaGetSymbolAddress((void**)&Slo,  g_Slo);
    cudaGetSymbolAddress((void**)&Ph,   g_Ph);
    cudaGetSymbolAddress((void**)&Pl,   g_Pl);
    cudaGetSymbolAddress((void**)&aeh,  g_aeh);
    cudaGetSymbolAddress((void**)&ael,  g_ael);
    cudaGetSymbolAddress((void**)&aTh,  g_aTh);
    cudaGetSymbolAddress((void**)&aTl,  g_aTl);
    cudaGetSymbolAddress((void**)&cath, g_cath);
    cudaGetSymbolAddress((void**)&catl, g_catl);
    cudaGetSymbolAddress((void**)&Wsh,  g_Wsh);
    cudaGetSymbolAddress((void**)&Wsl,  g_Wsl);
    cudaGetSymbolAddress((void**)&Woh,  g_Woh);
    cudaGetSymbolAddress((void**)&Wol,  g_Wol);

    cudaFuncSetAttribute(gemm_mma<0>, cudaFuncAttributeMaxDynamicSharedMemorySize, SMEM_SZ);
    cudaFuncSetAttribute(gemm_mma<1>, cudaFuncAttributeMaxDynamicSharedMemorySize, SMEM_SZ);
    cudaFuncSetAttribute(gemm_mma<2>, cudaFuncAttributeMaxDynamicSharedMemorySize, SMEM_SZ);

    // operand splits
    split_strided<<<(BB * HH) / 1024, 256>>>(attendee, aeh, ael, HH, HH);
    split_strided<<<(BB * HH) / 1024, 256>>>(attender, cath, catl, HH, 2 * HH);
    split_strided<<<(HH * HH) / 1024, 256>>>(W_score, Wsh, Wsl, HH, HH);
    split_strided<<<(HH * 2 * HH) / 1024, 256>>>(W_out, Woh, Wol, 2 * HH, 2 * HH);
    transpose_split<<<dim3(HH / 32, BB / 32), dim3(32, 8)>>>(attendee, aTh, aTl);

    // 1) P = attendee @ W_score^T + b_score  -> Ph/Pl              [8192,1024]
    gemm_mma<1><<<dim3(HH / TN, BB / TM), 256, SMEM_SZ>>>(
        aeh, ael, HH, Wsh, Wsl, HH, HH, b_score, nullptr, Ph, Pl, HH);
    // 2) S[j,i] = attender_j . P_i (fp32)                          [8192,8192]
    gemm_mma<0><<<dim3(BB / TN, BB / TM), 256, SMEM_SZ>>>(
        cath, catl, 2 * HH, Ph, Pl, HH, HH, nullptr, S, nullptr, nullptr, BB);
    // 3) softmax rows + split -> Shi/Slo
    softmax_split<<<BB, 256>>>(S, Shi, Slo);
    // 4) ctx = attn-rows @ attendee^T  -> cat cols [1024,2048)     [8192,1024]
    gemm_mma<1><<<dim3(HH / TN, BB / TM), 256, SMEM_SZ>>>(
        Shi, Slo, BB, aTh, aTl, BB, BB, nullptr, nullptr, cath + HH, catl + HH, 2 * HH);
    // 5) out = tanh(cat @ W_out^T + b_out)                         [8192,1024]
    gemm_mma<2><<<dim3(HH / TN, BB / TM), 256, SMEM_SZ>>>(
        cath, catl, 2 * HH, Woh, Wol, 2 * HH, 2 * HH, b_out, out, nullptr, nullptr, HH);
}